// round 3
// baseline (speedup 1.0000x reference)
#include <cuda_runtime.h>
#include <math.h>

// ---------------------------------------------------------------------------
// RelativePositionalEncoding: out[b,s,d] = nodes[b,s,d] +
//     (s <= num_nodes[b]) ? pe[(s - num_nodes[b]) mod 5000, d] : 0
// pe[p, 2j]   = sin(p * exp(2j * -ln(10000)/256))
// pe[p, 2j+1] = cos(p * exp(2j * -ln(10000)/256))
//
// B=32, S=4096, D=256, MAX_LEN=5000.
// ---------------------------------------------------------------------------

#define MAX_LEN 5000
#define B_DIM   32
#define S_DIM   4096
#define D_DIM   256
#define D4      (D_DIM / 4)          // 64 float4 per row

// Scratch: PE table, 5000 * 256 fp32 = 5.12 MB (device global, no allocation)
__device__ float g_pe[MAX_LEN * D_DIM];

// ---------------------------------------------------------------------------
// Prologue: build the PE table. 5000 rows * 128 (sin,cos) pairs = 640K sincosf.
// ---------------------------------------------------------------------------
__global__ void build_pe_kernel() {
    int gid = blockIdx.x * blockDim.x + threadIdx.x;
    const int total = MAX_LEN * (D_DIM / 2);          // 640000 pairs
    if (gid >= total) return;
    int pos = gid >> 7;                                // / 128
    int j   = gid & 127;                               // pair index -> dims (2j, 2j+1)
    // div = exp(2j * (-ln(10000)/256))
    float div = expf((float)(2 * j) * (-9.210340371976184f / 256.0f));
    float ang = (float)pos * div;
    float s, c;
    sincosf(ang, &s, &c);
    g_pe[pos * D_DIM + 2 * j]     = s;
    g_pe[pos * D_DIM + 2 * j + 1] = c;
}

// ---------------------------------------------------------------------------
// Main: float4-vectorized streaming add with masked PE gather.
// gid layout: d4 fastest (64 per row), then s (4096), then b (32).
// ---------------------------------------------------------------------------
__global__ void __launch_bounds__(256)
rpe_add_kernel(const float4* __restrict__ nodes,
               const int*    __restrict__ num_nodes,
               float4*       __restrict__ out) {
    unsigned gid = blockIdx.x * blockDim.x + threadIdx.x;
    // total float4 = 32*4096*64 = 8388608; grid sized exactly, no bounds check needed
    unsigned d4 = gid & (D4 - 1);
    unsigned sg = gid >> 6;                 // b*4096 + s
    unsigned s  = sg & (S_DIM - 1);
    unsigned b  = sg >> 12;

    int n = __ldg(&num_nodes[b]);

    float4 v = nodes[gid];
    if ((int)s <= n) {
        int idx = (int)s - n;               // in [-4095, 0]
        idx = (idx < 0) ? idx + MAX_LEN : 0;
        const float4* pe4 = reinterpret_cast<const float4*>(g_pe);
        float4 p = pe4[idx * D4 + d4];
        v.x += p.x; v.y += p.y; v.z += p.z; v.w += p.w;
    }
    out[gid] = v;
}

// ---------------------------------------------------------------------------
// Launch
// ---------------------------------------------------------------------------
extern "C" void kernel_launch(void* const* d_in, const int* in_sizes, int n_in,
                              void* d_out, int out_size) {
    const float4* nodes     = (const float4*)d_in[0];
    const int*    num_nodes = (const int*)d_in[1];
    float4*       out       = (float4*)d_out;

    // 1) Build PE table (640000 threads)
    {
        const int total = MAX_LEN * (D_DIM / 2);
        int threads = 256;
        int blocks  = (total + threads - 1) / threads;
        build_pe_kernel<<<blocks, threads>>>();
    }

    // 2) Streaming add. 32*4096*64 = 8388608 float4 -> 32768 blocks of 256.
    {
        const unsigned total4 = (unsigned)B_DIM * S_DIM * D4;
        int threads = 256;
        int blocks  = total4 / threads;
        rpe_add_kernel<<<blocks, threads>>>(nodes, num_nodes, out);
    }
}

// round 4
// speedup vs baseline: 1.0150x; 1.0150x over previous
#include <cuda_runtime.h>
#include <math.h>

// ---------------------------------------------------------------------------
// RelativePositionalEncoding: out[b,s,d] = nodes[b,s,d] +
//     (s <= num_nodes[b]) ? pe[(s - num_nodes[b]) mod 5000, d] : 0
// B=32, S=4096, D=256, MAX_LEN=5000.
// ---------------------------------------------------------------------------

#define MAX_LEN 5000
#define B_DIM   32
#define S_DIM   4096
#define D_DIM   256
#define D4      (D_DIM / 4)          // 64 float4 per row

// PE table scratch: 5000 * 256 fp32 = 5.12 MB
__device__ float g_pe[MAX_LEN * D_DIM];

// ---------------------------------------------------------------------------
// Prologue: build PE table, one float4 (= 2 sin/cos pairs) per thread.
// 5000 * 64 = 320000 threads, fully coalesced 16B stores.
// ---------------------------------------------------------------------------
__global__ void __launch_bounds__(256) build_pe_kernel() {
    int gid = blockIdx.x * blockDim.x + threadIdx.x;
    const int total = MAX_LEN * D4;                   // 320000 float4
    if (gid >= total) return;
    int pos = gid >> 6;                               // / 64
    int q   = gid & 63;                               // float4 index within row
    // float4 covers dims {4q, 4q+1, 4q+2, 4q+3} = pairs j0=2q, j1=2q+1
    const float c = -9.210340371976184f / 256.0f;     // -ln(10000)/256
    float div0 = expf((float)(4 * q)     * c);
    float div1 = expf((float)(4 * q + 2) * c);
    float fp = (float)pos;
    float s0, c0, s1, c1;
    sincosf(fp * div0, &s0, &c0);
    sincosf(fp * div1, &s1, &c1);
    float4 v = make_float4(s0, c0, s1, c1);
    reinterpret_cast<float4*>(g_pe)[gid] = v;
}

// ---------------------------------------------------------------------------
// Main: streaming add, 4 independent float4 per thread (MLP=4),
// evict-first hints on the streaming tensors to keep PE L2-resident.
// ---------------------------------------------------------------------------
#define VPT 4

__global__ void __launch_bounds__(256)
rpe_add_kernel(const float4* __restrict__ nodes,
               const int*    __restrict__ num_nodes,
               float4*       __restrict__ out) {
    const float4* pe4 = reinterpret_cast<const float4*>(g_pe);

    unsigned base = blockIdx.x * (blockDim.x * VPT) + threadIdx.x;

    unsigned idx_[VPT];
    float4   v[VPT];
    #pragma unroll
    for (int k = 0; k < VPT; k++) {
        idx_[k] = base + k * 256u;
        v[k] = __ldcs(&nodes[idx_[k]]);    // streaming read, evict-first
    }

    int   peOff[VPT];
    bool  msk[VPT];
    #pragma unroll
    for (int k = 0; k < VPT; k++) {
        unsigned gid = idx_[k];
        unsigned d4 = gid & (D4 - 1);
        unsigned sg = gid >> 6;            // b*4096 + s
        unsigned s  = sg & (S_DIM - 1);
        unsigned b  = sg >> 12;
        int n = __ldg(&num_nodes[b]);
        msk[k] = ((int)s <= n);
        int pidx = (int)s - n;             // [-4095, 0]
        pidx = (pidx < 0) ? pidx + MAX_LEN : 0;
        peOff[k] = pidx * D4 + (int)d4;
    }

    #pragma unroll
    for (int k = 0; k < VPT; k++) {
        if (msk[k]) {
            float4 p = __ldg(&pe4[peOff[k]]);  // L2-resident gather
            v[k].x += p.x; v[k].y += p.y; v[k].z += p.z; v[k].w += p.w;
        }
    }

    #pragma unroll
    for (int k = 0; k < VPT; k++) {
        __stcs(&out[idx_[k]], v[k]);       // streaming write, evict-first
    }
}

// ---------------------------------------------------------------------------
// Launch
// ---------------------------------------------------------------------------
extern "C" void kernel_launch(void* const* d_in, const int* in_sizes, int n_in,
                              void* d_out, int out_size) {
    const float4* nodes     = (const float4*)d_in[0];
    const int*    num_nodes = (const int*)d_in[1];
    float4*       out       = (float4*)d_out;

    // 1) Build PE table: 320000 float4
    {
        const int total = MAX_LEN * D4;
        int threads = 256;
        int blocks  = (total + threads - 1) / threads;
        build_pe_kernel<<<blocks, threads>>>();
    }

    // 2) Streaming add: 8388608 float4 / (256 threads * 4 per thread) = 8192 blocks
    {
        const unsigned total4 = (unsigned)B_DIM * S_DIM * D4;
        int threads = 256;
        int blocks  = total4 / (threads * VPT);
        rpe_add_kernel<<<blocks, threads>>>(nodes, num_nodes, out);
    }
}

// round 5
// speedup vs baseline: 1.0450x; 1.0295x over previous
#include <cuda_runtime.h>
#include <math.h>

// ---------------------------------------------------------------------------
// RelativePositionalEncoding: out[b,s,d] = nodes[b,s,d] +
//     (s <= num_nodes[b]) ? pe[(s - num_nodes[b]) mod 5000, d] : 0
// B=32, S=4096, D=256, MAX_LEN=5000.
// ---------------------------------------------------------------------------

#define MAX_LEN 5000
#define B_DIM   32
#define S_DIM   4096
#define D_DIM   256
#define D4      (D_DIM / 4)          // 64 float4 per row

// PE table scratch: 5000 * 256 fp32 = 5.12 MB
__device__ float g_pe[MAX_LEN * D_DIM];

// ---------------------------------------------------------------------------
// Prologue: build PE table with MUFU fast path.
// Angle = pos * div, max 4999 rad. Cody-Waite 2-term reduction to [-pi,pi],
// then __sinf/__cosf (pure MUFU on reduced range, abs err ~2^-21).
// One float4 (2 sin/cos pairs) per thread: 320000 threads, coalesced stores.
// ---------------------------------------------------------------------------
__device__ __forceinline__ void fast_sincos(float ang, float* s, float* c) {
    const float INV_2PI    = 0.15915493667125702f;   // 1/(2*pi)
    const float TWO_PI_HI  = 6.283185482025146f;     // float(2*pi)
    const float TWO_PI_LO  = -1.7484556000744947e-07f; // 2*pi - TWO_PI_HI
    float k = rintf(ang * INV_2PI);
    float r = fmaf(-k, TWO_PI_HI, ang);
    r = fmaf(-k, TWO_PI_LO, r);
    *s = __sinf(r);
    *c = __cosf(r);
}

__global__ void __launch_bounds__(256) build_pe_kernel() {
    int gid = blockIdx.x * blockDim.x + threadIdx.x;
    const int total = MAX_LEN * D4;                   // 320000 float4
    if (gid >= total) return;
    int pos = gid >> 6;                               // row
    int q   = gid & 63;                               // float4 index within row
    // div_j = 10000^(-2j/256) = 2^(2j * -log2(10000)/256), pairs j0=2q, j1=2q+1
    const float c2 = -13.287712379549449f / 256.0f;   // -log2(10000)/256
    float div0 = exp2f((float)(4 * q)     * c2);
    float div1 = exp2f((float)(4 * q + 2) * c2);
    float fp = (float)pos;
    float s0, c0, s1, c1;
    fast_sincos(fp * div0, &s0, &c0);
    fast_sincos(fp * div1, &s1, &c1);
    reinterpret_cast<float4*>(g_pe)[gid] = make_float4(s0, c0, s1, c1);
}

// ---------------------------------------------------------------------------
// Main: streaming add, 4 independent float4 per thread (MLP=4),
// evict-first hints on the streaming tensors; num_nodes hoisted (b is
// block-uniform: a block spans 1024 consecutive float4 = 16 rows, same b).
// ---------------------------------------------------------------------------
#define VPT 4

__global__ void __launch_bounds__(256)
rpe_add_kernel(const float4* __restrict__ nodes,
               const int*    __restrict__ num_nodes,
               float4*       __restrict__ out) {
    const float4* pe4 = reinterpret_cast<const float4*>(g_pe);

    unsigned base = blockIdx.x * (blockDim.x * VPT) + threadIdx.x;

    // b is uniform across the block (and across all VPT slices)
    unsigned b = base >> 18;                 // / (4096*64)
    int n = __ldg(&num_nodes[b]);

    unsigned idx_[VPT];
    float4   v[VPT];
    #pragma unroll
    for (int k = 0; k < VPT; k++) {
        idx_[k] = base + k * 256u;
        v[k] = __ldcs(&nodes[idx_[k]]);      // streaming read, evict-first
    }

    int  peOff[VPT];
    bool msk[VPT];
    #pragma unroll
    for (int k = 0; k < VPT; k++) {
        unsigned gid = idx_[k];
        unsigned d4 = gid & (D4 - 1);
        unsigned s  = (gid >> 6) & (S_DIM - 1);
        msk[k] = ((int)s <= n);
        int pidx = (int)s - n;               // [-4095, 0]
        pidx = (pidx < 0) ? pidx + MAX_LEN : 0;
        peOff[k] = pidx * D4 + (int)d4;
    }

    #pragma unroll
    for (int k = 0; k < VPT; k++) {
        if (msk[k]) {
            float4 p = __ldg(&pe4[peOff[k]]); // L2-resident gather
            v[k].x += p.x; v[k].y += p.y; v[k].z += p.z; v[k].w += p.w;
        }
    }

    #pragma unroll
    for (int k = 0; k < VPT; k++) {
        __stcs(&out[idx_[k]], v[k]);         // streaming write, evict-first
    }
}

// ---------------------------------------------------------------------------
// Launch
// ---------------------------------------------------------------------------
extern "C" void kernel_launch(void* const* d_in, const int* in_sizes, int n_in,
                              void* d_out, int out_size) {
    const float4* nodes     = (const float4*)d_in[0];
    const int*    num_nodes = (const int*)d_in[1];
    float4*       out       = (float4*)d_out;

    // 1) Build PE table: 320000 float4
    {
        const int total = MAX_LEN * D4;
        int threads = 256;
        int blocks  = (total + threads - 1) / threads;
        build_pe_kernel<<<blocks, threads>>>();
    }

    // 2) Streaming add: 8388608 float4 / (256 * 4) = 8192 blocks
    {
        const unsigned total4 = (unsigned)B_DIM * S_DIM * D4;
        int threads = 256;
        int blocks  = total4 / (threads * VPT);
        rpe_add_kernel<<<blocks, threads>>>(nodes, num_nodes, out);
    }
}

// round 7
// speedup vs baseline: 1.0934x; 1.0463x over previous
#include <cuda_runtime.h>
#include <math.h>

// ---------------------------------------------------------------------------
// RelativePositionalEncoding, fully fused (no PE table, no second kernel):
// out[b,s,d] = nodes[b,s,d] + (s <= n_b) ? pe[(s - n_b) mod 5000, d] : 0
// pe[p,2j] = sin(p*div_j), pe[p,2j+1] = cos(p*div_j),
// div_j = 10000^(-2j/256).  B=32, S=4096, D=256.
//
// Trig is computed inline: ~4 MUFU + ~10 FMA per masked float4, fully hidden
// under the DRAM-bound stream (issue was 15%, MUFU headroom ~2400 ops/cyc).
// ---------------------------------------------------------------------------

#define MAX_LEN 5000
#define B_DIM   32
#define S_DIM   4096
#define D_DIM   256
#define D4      (D_DIM / 4)          // 64 float4 per row
#define VPT     4

// Cody-Waite 2-term range reduction to [-pi,pi] + MUFU sin/cos.
// Max angle ~5000 rad -> k <= 796, reduction residual ~1e-11; MUFU abs err 2^-21.
__device__ __forceinline__ void fast_sincos(float ang, float* s, float* c) {
    const float INV_2PI   = 0.15915493667125702f;      // 1/(2*pi)
    const float TWO_PI_HI = 6.283185482025146f;        // float(2*pi)
    const float TWO_PI_LO = -1.7484556000744947e-07f;  // 2*pi - TWO_PI_HI
    float k = rintf(ang * INV_2PI);
    float r = fmaf(-k, TWO_PI_HI, ang);
    r = fmaf(-k, TWO_PI_LO, r);
    *s = __sinf(r);
    *c = __cosf(r);
}

__global__ void __launch_bounds__(256)
rpe_fused_kernel(const float4* __restrict__ nodes,
                 const int*    __restrict__ num_nodes,
                 float4*       __restrict__ out) {
    unsigned base = blockIdx.x * (blockDim.x * VPT) + threadIdx.x;

    // b uniform across block; d4 invariant across the VPT slices (stride 256).
    unsigned b  = base >> 18;                 // / (4096*64)
    unsigned d4 = base & (D4 - 1);
    int n = __ldg(&num_nodes[b]);

    // div_j = 2^(2j * -log2(10000)/256); this float4 covers pairs j0=2*d4, j1=2*d4+1
    const float c2 = -13.287712379549449f / 256.0f;    // -log2(10000)/256
    float div0 = exp2f((float)(4 * d4)     * c2);
    float div1 = exp2f((float)(4 * d4 + 2) * c2);

    // Front-batched streaming loads (MLP=4), evict-first.
    unsigned idx_[VPT];
    float4   v[VPT];
    #pragma unroll
    for (int k = 0; k < VPT; k++) {
        idx_[k] = base + k * 256u;
        v[k] = __ldcs(&nodes[idx_[k]]);
    }

    #pragma unroll
    for (int k = 0; k < VPT; k++) {
        unsigned s = (idx_[k] >> 6) & (S_DIM - 1);
        if ((int)s <= n) {                    // warp-uniform predicate
            int p = (int)s - n;               // [-4095, 0]
            p = (p < 0) ? p + MAX_LEN : 0;
            float fp = (float)p;              // exact in fp32 (p < 2^13)
            float s0, c0, s1, c1;
            fast_sincos(fp * div0, &s0, &c0);
            fast_sincos(fp * div1, &s1, &c1);
            v[k].x += s0; v[k].y += c0; v[k].z += s1; v[k].w += c1;
        }
    }

    #pragma unroll
    for (int k = 0; k < VPT; k++) {
        __stcs(&out[idx_[k]], v[k]);          // streaming write, evict-first
    }
}

// ---------------------------------------------------------------------------
// Launch: single kernel, 8388608 float4 / (256 threads * 4) = 8192 blocks.
// ---------------------------------------------------------------------------
extern "C" void kernel_launch(void* const* d_in, const int* in_sizes, int n_in,
                              void* d_out, int out_size) {
    const float4* nodes     = (const float4*)d_in[0];
    const int*    num_nodes = (const int*)d_in[1];
    float4*       out       = (float4*)d_out;

    const unsigned total4 = (unsigned)B_DIM * S_DIM * D4;
    int threads = 256;
    int blocks  = total4 / (threads * VPT);
    rpe_fused_kernel<<<blocks, threads>>>(nodes, num_nodes, out);
}